// round 4
// baseline (speedup 1.0000x reference)
#include <cuda_runtime.h>
#include <math.h>

#define ALPHA 0.7f
#define EPS 1e-7f

#define NBLOCKS (148 * 16)   // 2368
#define NTHREADS 256

__device__ float g_partials[NBLOCKS];
__device__ unsigned int g_ticket;   // zero at load; last block resets each call

__device__ __forceinline__ float focal_quad(float4 p, int4 y) {
    float s = 0.0f;
    {
        bool pos = (y.x == 1);
        float pt = pos ? p.x : 1.0f - p.x;
        float l  = -__logf(pt);
        if (isinf(l)) l = EPS;
        float om = 1.0f - pt;
        float f  = om * om * l;
        s += pos ? f * ALPHA : f;
    }
    {
        bool pos = (y.y == 1);
        float pt = pos ? p.y : 1.0f - p.y;
        float l  = -__logf(pt);
        if (isinf(l)) l = EPS;
        float om = 1.0f - pt;
        float f  = om * om * l;
        s += pos ? f * ALPHA : f;
    }
    {
        bool pos = (y.z == 1);
        float pt = pos ? p.z : 1.0f - p.z;
        float l  = -__logf(pt);
        if (isinf(l)) l = EPS;
        float om = 1.0f - pt;
        float f  = om * om * l;
        s += pos ? f * ALPHA : f;
    }
    {
        bool pos = (y.w == 1);
        float pt = pos ? p.w : 1.0f - p.w;
        float l  = -__logf(pt);
        if (isinf(l)) l = EPS;
        float om = 1.0f - pt;
        float f  = om * om * l;
        s += pos ? f * ALPHA : f;
    }
    return s;
}

__global__ void __launch_bounds__(NTHREADS) focal_fused_kernel(
    const float* __restrict__ p_in,
    const int*   __restrict__ y_in,
    unsigned int n4,       // number of float4 quads (fits in u32)
    long long n,           // total elements
    float* __restrict__ out)
{
    const float4* __restrict__ p4 = (const float4*)p_in;
    const int4*   __restrict__ y4 = (const int4*)y_in;

    float acc = 0.0f;

    const unsigned int idx    = blockIdx.x * (unsigned int)blockDim.x + threadIdx.x;
    const unsigned int stride = gridDim.x * (unsigned int)blockDim.x;

    unsigned int i = idx;

    // 4-way unrolled main loop: front-batch 8 independent LDG.128s (streaming)
    for (; i + 3u * stride < n4; i += 4u * stride) {
        float4 p0 = __ldcs(&p4[i]);
        float4 p1 = __ldcs(&p4[i +      stride]);
        float4 p2 = __ldcs(&p4[i + 2u * stride]);
        float4 p3 = __ldcs(&p4[i + 3u * stride]);
        int4   y0 = __ldcs(&y4[i]);
        int4   y1 = __ldcs(&y4[i +      stride]);
        int4   y2 = __ldcs(&y4[i + 2u * stride]);
        int4   y3 = __ldcs(&y4[i + 3u * stride]);

        acc += focal_quad(p0, y0);
        acc += focal_quad(p1, y1);
        acc += focal_quad(p2, y2);
        acc += focal_quad(p3, y3);
    }
    // tail
    for (; i < n4; i += stride) {
        float4 p = __ldcs(&p4[i]);
        int4   y = __ldcs(&y4[i]);
        acc += focal_quad(p, y);
    }

    // ---- intra-block reduction ----
    #pragma unroll
    for (int off = 16; off > 0; off >>= 1)
        acc += __shfl_xor_sync(0xFFFFFFFFu, acc, off);

    __shared__ float warp_sums[NTHREADS / 32];
    __shared__ bool  s_is_last;
    int lane = threadIdx.x & 31;
    int wid  = threadIdx.x >> 5;
    if (lane == 0) warp_sums[wid] = acc;
    __syncthreads();

    if (threadIdx.x == 0) {
        float bs = 0.0f;
        #pragma unroll
        for (int w = 0; w < NTHREADS / 32; w++) bs += warp_sums[w];
        g_partials[blockIdx.x] = bs;
        __threadfence();
        unsigned int t = atomicAdd(&g_ticket, 1u);
        s_is_last = (t == gridDim.x - 1);
    }
    __syncthreads();

    // ---- last block performs the final reduction ----
    if (s_is_last) {
        float v = 0.0f;
        for (unsigned int j = threadIdx.x; j < gridDim.x; j += NTHREADS)
            v += g_partials[j];

        #pragma unroll
        for (int off = 16; off > 0; off >>= 1)
            v += __shfl_xor_sync(0xFFFFFFFFu, v, off);

        if (lane == 0) warp_sums[wid] = v;
        __syncthreads();

        if (threadIdx.x == 0) {
            float total = 0.0f;
            #pragma unroll
            for (int w = 0; w < NTHREADS / 32; w++) total += warp_sums[w];
            out[0] = (float)((double)total / (double)n);
            g_ticket = 0;   // reset for next graph replay
        }
    }
}

extern "C" void kernel_launch(void* const* d_in, const int* in_sizes, int n_in,
                              void* d_out, int out_size) {
    const float* p = (const float*)d_in[0];
    const int*   y = (const int*)d_in[1];
    float* out = (float*)d_out;

    long long n  = (long long)in_sizes[0];
    unsigned int n4 = (unsigned int)(n / 4);   // 7,077,888 quads

    int blocks = NBLOCKS;
    long long needed = ((long long)n4 + NTHREADS - 1) / NTHREADS;
    if ((long long)blocks > needed) blocks = (int)needed;

    focal_fused_kernel<<<blocks, NTHREADS>>>(p, y, n4, n, out);
}

// round 5
// speedup vs baseline: 1.0625x; 1.0625x over previous
#include <cuda_runtime.h>
#include <math.h>

#define ALPHA 0.7f
#define EPS 1e-7f

#define NBLOCKS (148 * 8)   // 1184: one fully-resident wave at 8 blocks/SM (32 regs)
#define NTHREADS 256

__device__ float g_partials[NBLOCKS];
__device__ unsigned int g_ticket;   // zero at load; last block resets each call

__global__ void __launch_bounds__(NTHREADS) focal_fused_kernel(
    const float* __restrict__ p_in,
    const int*   __restrict__ y_in,
    long long n4,          // number of float4 quads
    long long n,           // total elements
    float* __restrict__ out)
{
    const float4* __restrict__ p4 = (const float4*)p_in;
    const int4*   __restrict__ y4 = (const int4*)y_in;

    float acc = 0.0f;

    long long idx    = (long long)blockIdx.x * blockDim.x + threadIdx.x;
    long long stride = (long long)gridDim.x * blockDim.x;

    for (long long i = idx; i < n4; i += stride) {
        float4 p = p4[i];
        int4   y = y4[i];

        {
            bool pos = (y.x == 1);
            float pt = pos ? p.x : 1.0f - p.x;
            float l  = -__logf(pt);
            if (isinf(l)) l = EPS;
            float om = 1.0f - pt;
            float f  = om * om * l;
            acc += pos ? f * ALPHA : f;
        }
        {
            bool pos = (y.y == 1);
            float pt = pos ? p.y : 1.0f - p.y;
            float l  = -__logf(pt);
            if (isinf(l)) l = EPS;
            float om = 1.0f - pt;
            float f  = om * om * l;
            acc += pos ? f * ALPHA : f;
        }
        {
            bool pos = (y.z == 1);
            float pt = pos ? p.z : 1.0f - p.z;
            float l  = -__logf(pt);
            if (isinf(l)) l = EPS;
            float om = 1.0f - pt;
            float f  = om * om * l;
            acc += pos ? f * ALPHA : f;
        }
        {
            bool pos = (y.w == 1);
            float pt = pos ? p.w : 1.0f - p.w;
            float l  = -__logf(pt);
            if (isinf(l)) l = EPS;
            float om = 1.0f - pt;
            float f  = om * om * l;
            acc += pos ? f * ALPHA : f;
        }
    }

    // ---- intra-block reduction ----
    #pragma unroll
    for (int off = 16; off > 0; off >>= 1)
        acc += __shfl_xor_sync(0xFFFFFFFFu, acc, off);

    __shared__ float warp_sums[NTHREADS / 32];
    __shared__ bool  s_is_last;
    int lane = threadIdx.x & 31;
    int wid  = threadIdx.x >> 5;
    if (lane == 0) warp_sums[wid] = acc;
    __syncthreads();

    if (threadIdx.x == 0) {
        float bs = 0.0f;
        #pragma unroll
        for (int w = 0; w < NTHREADS / 32; w++) bs += warp_sums[w];
        g_partials[blockIdx.x] = bs;
        __threadfence();
        unsigned int t = atomicAdd(&g_ticket, 1u);
        s_is_last = (t == gridDim.x - 1);
    }
    __syncthreads();

    // ---- last block performs the final reduction ----
    if (s_is_last) {
        float v = 0.0f;
        for (unsigned int j = threadIdx.x; j < gridDim.x; j += NTHREADS)
            v += g_partials[j];

        #pragma unroll
        for (int off = 16; off > 0; off >>= 1)
            v += __shfl_xor_sync(0xFFFFFFFFu, v, off);

        if (lane == 0) warp_sums[wid] = v;
        __syncthreads();

        if (threadIdx.x == 0) {
            float total = 0.0f;
            #pragma unroll
            for (int w = 0; w < NTHREADS / 32; w++) total += warp_sums[w];
            out[0] = (float)((double)total / (double)n);
            g_ticket = 0;   // reset for next graph replay
        }
    }
}

extern "C" void kernel_launch(void* const* d_in, const int* in_sizes, int n_in,
                              void* d_out, int out_size) {
    const float* p = (const float*)d_in[0];
    const int*   y = (const int*)d_in[1];
    float* out = (float*)d_out;

    long long n  = (long long)in_sizes[0];
    long long n4 = n / 4;   // 7,077,888 quads

    int blocks = NBLOCKS;
    long long needed = (n4 + NTHREADS - 1) / NTHREADS;
    if ((long long)blocks > needed) blocks = (int)needed;

    focal_fused_kernel<<<blocks, NTHREADS>>>(p, y, n4, n, out);
}